// round 1
// baseline (speedup 1.0000x reference)
#include <cuda_runtime.h>
#include <cstddef>

// Multi-scale deformable attention, specialized to:
// B=2, nH=8, D=32, Q=21760, L=4, P=4, levels {128,64,32,16}^2 (squares)
// value:  (B, Len, nH, D)            f32   Len = 21760
// locs:   (B, Q, nH, L, P, 2)        f32   (normalized [0,1] coords)
// attw:   (B, Q, nH, L, P)           f32
// out:    (B, Q, nH*D)               f32
//
// Mapping: blockDim=256. Each 8-lane group handles one query's 4 channels
// (float4); a warp covers 4 queries; a block covers 32 queries of one (b,h).
// grid = (Q/32, B*nH).

namespace {

constexpr int B   = 2;
constexpr int nH  = 8;
constexpr int D   = 32;
constexpr int Q   = 21760;
constexpr int Len = 21760;
constexpr int QPB = 32;                 // queries per block
constexpr int CH_STRIDE = nH * D;       // 256 floats between spatial indices

__global__ __launch_bounds__(256, 8)
void msda_kernel(const float* __restrict__ value,
                 const float* __restrict__ locs,
                 const float* __restrict__ attw,
                 float* __restrict__ out)
{
    // level tables (compile-time)
    constexpr int levW[4]     = {128, 64, 32, 16};
    constexpr int levStart[4] = {0, 16384, 20480, 21504};

    __shared__ float s_loc[QPB][33];   // 32 floats/query (L*P*2), padded
    __shared__ float s_w[QPB][17];     // 16 floats/query, padded

    const int bh = blockIdx.y;
    const int b  = bh >> 3;
    const int h  = bh & 7;
    const int q0 = blockIdx.x * QPB;
    const int tid = threadIdx.x;

    // ---- cooperative stage of per-query scalars ----
    // locs for fixed (b,q,h): 32 contiguous floats at (b*Q+q)*256 + h*32
    #pragma unroll
    for (int i = tid; i < QPB * 32; i += 256) {
        const int qi = i >> 5, j = i & 31;
        s_loc[qi][j] = locs[(size_t)(b * Q + q0 + qi) * 256 + h * 32 + j];
    }
    // weights for fixed (b,q,h): 16 contiguous floats at (b*Q+q)*128 + h*16
    #pragma unroll
    for (int i = tid; i < QPB * 16; i += 256) {
        const int qi = i >> 4, j = i & 15;
        s_w[qi][j] = attw[(size_t)(b * Q + q0 + qi) * 128 + h * 16 + j];
    }
    __syncthreads();

    const int lane = tid & 31;
    const int warp = tid >> 5;
    const int qsub = warp * 4 + (lane >> 3);   // 0..31 query within block
    const int cg   = lane & 7;                 // channel group: channels cg*4..cg*4+3
    const int q    = q0 + qsub;

    // value base for (b,h) at our channel group
    const float* vbase = value + (size_t)b * Len * CH_STRIDE + h * D + cg * 4;

    float4 acc = make_float4(0.f, 0.f, 0.f, 0.f);

    #pragma unroll
    for (int pt = 0; pt < 16; ++pt) {
        const int l = pt >> 2;
        const int W = levW[l];            // H == W (square levels)
        const int start = levStart[l];

        const float lx = s_loc[qsub][pt * 2 + 0];
        const float ly = s_loc[qsub][pt * 2 + 1];
        const float aw = s_w[qsub][pt];

        // pixel coords: x = loc*W - 0.5 (derived from grid_sample align_corners=False)
        const float x = lx * (float)W - 0.5f;
        const float y = ly * (float)W - 0.5f;

        const float x0f = floorf(x);
        const float y0f = floorf(y);
        const int   x0  = (int)x0f;
        const int   y0  = (int)y0f;
        const float wx1 = x - x0f;
        const float wy1 = y - y0f;
        const float wx0 = 1.f - wx1;
        const float wy0 = 1.f - wy1;

        const bool vx0 = (x0 >= 0) && (x0 < W);
        const bool vx1 = (x0 + 1 >= 0) && (x0 + 1 < W);
        const bool vy0 = (y0 >= 0) && (y0 < W);
        const bool vy1 = (y0 + 1 >= 0) && (y0 + 1 < W);

        const float w00 = wy0 * wx0 * aw;
        const float w01 = wy0 * wx1 * aw;
        const float w10 = wy1 * wx0 * aw;
        const float w11 = wy1 * wx1 * aw;

        const float* p00 = vbase + (size_t)(start + y0 * W + x0) * CH_STRIDE;

        if (vy0 && vx0) {
            const float4 v = *reinterpret_cast<const float4*>(p00);
            acc.x += w00 * v.x; acc.y += w00 * v.y; acc.z += w00 * v.z; acc.w += w00 * v.w;
        }
        if (vy0 && vx1) {
            const float4 v = *reinterpret_cast<const float4*>(p00 + CH_STRIDE);
            acc.x += w01 * v.x; acc.y += w01 * v.y; acc.z += w01 * v.z; acc.w += w01 * v.w;
        }
        if (vy1 && vx0) {
            const float4 v = *reinterpret_cast<const float4*>(p00 + (size_t)W * CH_STRIDE);
            acc.x += w10 * v.x; acc.y += w10 * v.y; acc.z += w10 * v.z; acc.w += w10 * v.w;
        }
        if (vy1 && vx1) {
            const float4 v = *reinterpret_cast<const float4*>(p00 + (size_t)(W + 1) * CH_STRIDE);
            acc.x += w11 * v.x; acc.y += w11 * v.y; acc.z += w11 * v.z; acc.w += w11 * v.w;
        }
    }

    // out[b][q][h*32 + cg*4 .. +3]
    float4* outp = reinterpret_cast<float4*>(out + (size_t)(b * Q + q) * (nH * D) + h * D + cg * 4);
    *outp = acc;
}

} // namespace

extern "C" void kernel_launch(void* const* d_in, const int* in_sizes, int n_in,
                              void* d_out, int out_size)
{
    const float* value = (const float*)d_in[0];
    // d_in[1]: value_spatial_shapes (int64) — compile-time constant, ignored
    // d_in[2]: value_level_start_index (int64) — compile-time constant, ignored
    const float* locs  = (const float*)d_in[3];
    const float* attw  = (const float*)d_in[4];
    // d_in[5]: im2col_step — ignored
    float* out = (float*)d_out;

    dim3 grid(Q / QPB, B * nH);   // (680, 16)
    msda_kernel<<<grid, 256>>>(value, locs, attw, out);
}

// round 2
// speedup vs baseline: 1.0004x; 1.0004x over previous
#include <cuda_runtime.h>
#include <cstddef>

// Multi-scale deformable attention, specialized to:
// B=2, nH=8, D=32, Q=21760, L=4, P=4, levels {128,64,32,16}^2 (squares)
// value:  (B, Len, nH, D)            f32   Len = 21760
// locs:   (B, Q, nH, L, P, 2)        f32   (normalized [0,1] coords)
// attw:   (B, Q, nH, L, P)           f32
// out:    (B, Q, nH*D)               f32
//
// Mapping: blockDim=256. Each 8-lane group handles one query's 4 channels
// (float4); a warp covers 4 queries; a block covers 32 queries of one (b,h).
// grid = (Q/32, B*nH).

namespace {

constexpr int B   = 2;
constexpr int nH  = 8;
constexpr int D   = 32;
constexpr int Q   = 21760;
constexpr int Len = 21760;
constexpr int QPB = 32;                 // queries per block
constexpr int CH_STRIDE = nH * D;       // 256 floats between spatial indices

__global__ __launch_bounds__(256, 8)
void msda_kernel(const float* __restrict__ value,
                 const float* __restrict__ locs,
                 const float* __restrict__ attw,
                 float* __restrict__ out)
{
    // level tables (compile-time)
    constexpr int levW[4]     = {128, 64, 32, 16};
    constexpr int levStart[4] = {0, 16384, 20480, 21504};

    __shared__ float s_loc[QPB][33];   // 32 floats/query (L*P*2), padded
    __shared__ float s_w[QPB][17];     // 16 floats/query, padded

    const int bh = blockIdx.y;
    const int b  = bh >> 3;
    const int h  = bh & 7;
    const int q0 = blockIdx.x * QPB;
    const int tid = threadIdx.x;

    // ---- cooperative stage of per-query scalars ----
    // locs for fixed (b,q,h): 32 contiguous floats at (b*Q+q)*256 + h*32
    #pragma unroll
    for (int i = tid; i < QPB * 32; i += 256) {
        const int qi = i >> 5, j = i & 31;
        s_loc[qi][j] = locs[(size_t)(b * Q + q0 + qi) * 256 + h * 32 + j];
    }
    // weights for fixed (b,q,h): 16 contiguous floats at (b*Q+q)*128 + h*16
    #pragma unroll
    for (int i = tid; i < QPB * 16; i += 256) {
        const int qi = i >> 4, j = i & 15;
        s_w[qi][j] = attw[(size_t)(b * Q + q0 + qi) * 128 + h * 16 + j];
    }
    __syncthreads();

    const int lane = tid & 31;
    const int warp = tid >> 5;
    const int qsub = warp * 4 + (lane >> 3);   // 0..31 query within block
    const int cg   = lane & 7;                 // channel group: channels cg*4..cg*4+3
    const int q    = q0 + qsub;

    // value base for (b,h) at our channel group
    const float* vbase = value + (size_t)b * Len * CH_STRIDE + h * D + cg * 4;

    float4 acc = make_float4(0.f, 0.f, 0.f, 0.f);

    #pragma unroll
    for (int pt = 0; pt < 16; ++pt) {
        const int l = pt >> 2;
        const int W = levW[l];            // H == W (square levels)
        const int start = levStart[l];

        const float lx = s_loc[qsub][pt * 2 + 0];
        const float ly = s_loc[qsub][pt * 2 + 1];
        const float aw = s_w[qsub][pt];

        // pixel coords: x = loc*W - 0.5 (derived from grid_sample align_corners=False)
        const float x = lx * (float)W - 0.5f;
        const float y = ly * (float)W - 0.5f;

        const float x0f = floorf(x);
        const float y0f = floorf(y);
        const int   x0  = (int)x0f;
        const int   y0  = (int)y0f;
        const float wx1 = x - x0f;
        const float wy1 = y - y0f;
        const float wx0 = 1.f - wx1;
        const float wy0 = 1.f - wy1;

        const bool vx0 = (x0 >= 0) && (x0 < W);
        const bool vx1 = (x0 + 1 >= 0) && (x0 + 1 < W);
        const bool vy0 = (y0 >= 0) && (y0 < W);
        const bool vy1 = (y0 + 1 >= 0) && (y0 + 1 < W);

        const float w00 = wy0 * wx0 * aw;
        const float w01 = wy0 * wx1 * aw;
        const float w10 = wy1 * wx0 * aw;
        const float w11 = wy1 * wx1 * aw;

        const float* p00 = vbase + (size_t)(start + y0 * W + x0) * CH_STRIDE;

        if (vy0 && vx0) {
            const float4 v = *reinterpret_cast<const float4*>(p00);
            acc.x += w00 * v.x; acc.y += w00 * v.y; acc.z += w00 * v.z; acc.w += w00 * v.w;
        }
        if (vy0 && vx1) {
            const float4 v = *reinterpret_cast<const float4*>(p00 + CH_STRIDE);
            acc.x += w01 * v.x; acc.y += w01 * v.y; acc.z += w01 * v.z; acc.w += w01 * v.w;
        }
        if (vy1 && vx0) {
            const float4 v = *reinterpret_cast<const float4*>(p00 + (size_t)W * CH_STRIDE);
            acc.x += w10 * v.x; acc.y += w10 * v.y; acc.z += w10 * v.z; acc.w += w10 * v.w;
        }
        if (vy1 && vx1) {
            const float4 v = *reinterpret_cast<const float4*>(p00 + (size_t)(W + 1) * CH_STRIDE);
            acc.x += w11 * v.x; acc.y += w11 * v.y; acc.z += w11 * v.z; acc.w += w11 * v.w;
        }
    }

    // out[b][q][h*32 + cg*4 .. +3]
    float4* outp = reinterpret_cast<float4*>(out + (size_t)(b * Q + q) * (nH * D) + h * D + cg * 4);
    *outp = acc;
}

} // namespace

extern "C" void kernel_launch(void* const* d_in, const int* in_sizes, int n_in,
                              void* d_out, int out_size)
{
    const float* value = (const float*)d_in[0];
    // d_in[1]: value_spatial_shapes (int64) — compile-time constant, ignored
    // d_in[2]: value_level_start_index (int64) — compile-time constant, ignored
    const float* locs  = (const float*)d_in[3];
    const float* attw  = (const float*)d_in[4];
    // d_in[5]: im2col_step — ignored
    float* out = (float*)d_out;

    dim3 grid(Q / QPB, B * nH);   // (680, 16)
    msda_kernel<<<grid, 256>>>(value, locs, attw, out);
}